// round 1
// baseline (speedup 1.0000x reference)
#include <cuda_runtime.h>
#include <math.h>

#define Bq   2048
#define Nn_  65536
#define Aa   512
#define Dd   512
#define TOPK 8

// -------- scratch (device globals: allocation-free per harness rules) --------
__device__ float g_sim[(size_t)Bq * Nn_];   // 512 MB sim matrix
__device__ float g_q[Bq * Aa];              // projected+normalized query
__device__ float g_invn[Nn_];               // 1/||addr_row||
__device__ float g_tv[Bq * TOPK];           // top-k sims
__device__ int   g_ti[Bq * TOPK];           // top-k indices

// -------- per-row inverse norms of addr_buf (warp per row) --------
__global__ void inv_norm_kernel(const float* __restrict__ addr) {
    int warp = threadIdx.x >> 5, lane = threadIdx.x & 31;
    int row = blockIdx.x * 8 + warp;
    const float4* p = (const float4*)(addr + (size_t)row * Aa);
    float s = 0.f;
#pragma unroll
    for (int i = 0; i < 4; i++) {
        float4 v = p[lane + 32 * i];
        s += v.x * v.x + v.y * v.y + v.z * v.z + v.w * v.w;
    }
#pragma unroll
    for (int o = 16; o > 0; o >>= 1) s += __shfl_xor_sync(0xffffffffu, s, o);
    if (lane == 0) g_invn[row] = 1.f / fmaxf(sqrtf(s), 1e-12f);
}

// -------- tiled SGEMM-NT: C[m,n] = (sum_k A[m,k]*B[n,k]) * scale[n] + bias[n] --------
// BM=BN=128, BK=16, 256 threads, 8x8 per-thread microtile. All dims divide evenly.
template<int NCOLS, int K, bool SCALE, bool BIAS>
__global__ void __launch_bounds__(256, 2)
gemm_nt(const float* __restrict__ A, const float* __restrict__ Bm,
        float* __restrict__ C, const float* __restrict__ bias)
{
    constexpr int BM = 128, BN = 128, BK = 16;
    __shared__ float sA[BK][BM];
    __shared__ float sB[BK][BN];
    const int tid = threadIdx.x;
    const int tx = tid & 15, ty = tid >> 4;
    const int m0 = blockIdx.y * BM, n0 = blockIdx.x * BN;

    float acc[8][8];
#pragma unroll
    for (int i = 0; i < 8; i++)
#pragma unroll
        for (int j = 0; j < 8; j++) acc[i][j] = 0.f;

    for (int k0 = 0; k0 < K; k0 += BK) {
#pragma unroll
        for (int i = 0; i < 2; i++) {
            int idx = tid + i * 256;
            int r = idx >> 2, c = (idx & 3) * 4;
            float4 va = *(const float4*)(A + (size_t)(m0 + r) * K + k0 + c);
            sA[c + 0][r] = va.x; sA[c + 1][r] = va.y;
            sA[c + 2][r] = va.z; sA[c + 3][r] = va.w;
            float4 vb = *(const float4*)(Bm + (size_t)(n0 + r) * K + k0 + c);
            sB[c + 0][r] = vb.x; sB[c + 1][r] = vb.y;
            sB[c + 2][r] = vb.z; sB[c + 3][r] = vb.w;
        }
        __syncthreads();
#pragma unroll
        for (int kk = 0; kk < BK; kk++) {
            float ra[8], rb[8];
            *(float4*)&ra[0] = *(const float4*)&sA[kk][ty * 8];
            *(float4*)&ra[4] = *(const float4*)&sA[kk][ty * 8 + 4];
            *(float4*)&rb[0] = *(const float4*)&sB[kk][tx * 8];
            *(float4*)&rb[4] = *(const float4*)&sB[kk][tx * 8 + 4];
#pragma unroll
            for (int i = 0; i < 8; i++)
#pragma unroll
                for (int j = 0; j < 8; j++)
                    acc[i][j] = fmaf(ra[i], rb[j], acc[i][j]);
        }
        __syncthreads();
    }

    float scl[8], bi[8];
#pragma unroll
    for (int j = 0; j < 8; j++) {
        int n = n0 + tx * 8 + j;
        scl[j] = SCALE ? g_invn[n] : 1.f;
        bi[j]  = BIAS ? bias[n] : 0.f;
    }
#pragma unroll
    for (int i = 0; i < 8; i++) {
        int m = m0 + ty * 8 + i;
        float* crow = C + (size_t)m * NCOLS + n0 + tx * 8;
        float o[8];
#pragma unroll
        for (int j = 0; j < 8; j++) o[j] = acc[i][j] * scl[j] + bi[j];
        *(float4*)&crow[0] = *(float4*)&o[0];
        *(float4*)&crow[4] = *(float4*)&o[4];
    }
}

// -------- L2-normalize rows of g_q in place (block per row, 128 threads) --------
__global__ void qnorm_kernel() {
    int row = blockIdx.x;
    float4* p = (float4*)(g_q + (size_t)row * Aa);
    int tid = threadIdx.x;
    float4 v = p[tid];
    float s = v.x * v.x + v.y * v.y + v.z * v.z + v.w * v.w;
#pragma unroll
    for (int o = 16; o > 0; o >>= 1) s += __shfl_xor_sync(0xffffffffu, s, o);
    __shared__ float ws[4];
    if ((tid & 31) == 0) ws[tid >> 5] = s;
    __syncthreads();
    float tot = ws[0] + ws[1] + ws[2] + ws[3];
    float inv = 1.f / fmaxf(sqrtf(tot), 1e-12f);
    v.x *= inv; v.y *= inv; v.z *= inv; v.w *= inv;
    p[tid] = v;
}

// -------- top-8 per row (block per row, 256 threads) --------
__global__ void __launch_bounds__(256) topk_kernel() {
    int row = blockIdx.x;
    const float* s = g_sim + (size_t)row * Nn_;
    int tid = threadIdx.x;

    float lv[TOPK]; int li[TOPK];
#pragma unroll
    for (int k = 0; k < TOPK; k++) { lv[k] = -INFINITY; li[k] = 0; }

    for (int n = tid; n < Nn_; n += 256) {
        float v = s[n];
        if (v > lv[TOPK - 1]) {
            lv[TOPK - 1] = v; li[TOPK - 1] = n;
#pragma unroll
            for (int q = TOPK - 1; q > 0; q--) {
                if (lv[q] > lv[q - 1]) {
                    float tv = lv[q]; lv[q] = lv[q - 1]; lv[q - 1] = tv;
                    int   ti = li[q]; li[q] = li[q - 1]; li[q - 1] = ti;
                }
            }
        }
    }

    __shared__ float sv[256 * TOPK];
    __shared__ int   si[256 * TOPK];
    __shared__ float rv[256];
    __shared__ int   rp[256];
#pragma unroll
    for (int k = 0; k < TOPK; k++) { sv[tid * TOPK + k] = lv[k]; si[tid * TOPK + k] = li[k]; }
    __syncthreads();

    for (int k = 0; k < TOPK; k++) {
        float best = -INFINITY; int bp = 0;
        for (int j = tid; j < 256 * TOPK; j += 256)
            if (sv[j] > best) { best = sv[j]; bp = j; }
        rv[tid] = best; rp[tid] = bp;
        __syncthreads();
        for (int off = 128; off > 0; off >>= 1) {
            if (tid < off) {
                if (rv[tid + off] > rv[tid]) { rv[tid] = rv[tid + off]; rp[tid] = rp[tid + off]; }
            }
            __syncthreads();
        }
        if (tid == 0) {
            g_tv[row * TOPK + k] = rv[0];
            g_ti[row * TOPK + k] = si[rp[0]];
            sv[rp[0]] = -INFINITY;
        }
        __syncthreads();
    }
}

// -------- softmax(10*sim) weighted gather of data rows (block per row) --------
__global__ void gather_kernel(const float* __restrict__ data, float* __restrict__ out) {
    int row = blockIdx.x;
    int tid = threadIdx.x;  // 128 threads, one float4 each over D=512
    float w[TOPK]; int ix[TOPK];
    float m = -INFINITY;
#pragma unroll
    for (int k = 0; k < TOPK; k++) {
        w[k] = g_tv[row * TOPK + k];
        ix[k] = g_ti[row * TOPK + k];
        m = fmaxf(m, w[k]);
    }
    float sum = 0.f;
#pragma unroll
    for (int k = 0; k < TOPK; k++) { w[k] = expf((w[k] - m) * 10.f); sum += w[k]; }
    float inv = 1.f / sum;

    float4 accv = make_float4(0.f, 0.f, 0.f, 0.f);
#pragma unroll
    for (int k = 0; k < TOPK; k++) {
        float4 v = *(const float4*)(data + (size_t)ix[k] * Dd + tid * 4);
        float wk = w[k] * inv;
        accv.x += wk * v.x; accv.y += wk * v.y;
        accv.z += wk * v.z; accv.w += wk * v.w;
    }
    *(float4*)(out + (size_t)row * Dd + tid * 4) = accv;
}

extern "C" void kernel_launch(void* const* d_in, const int* in_sizes, int n_in,
                              void* d_out, int out_size) {
    const float* query = (const float*)d_in[0];
    const float* addr  = (const float*)d_in[1];
    const float* data  = (const float*)d_in[2];
    const float* W     = (const float*)d_in[3];
    const float* bias  = (const float*)d_in[4];
    float* out = (float*)d_out;

    void *qp = nullptr, *simp = nullptr;
    cudaGetSymbolAddress(&qp, g_q);
    cudaGetSymbolAddress(&simp, g_sim);
    float* qptr   = (float*)qp;
    float* simptr = (float*)simp;

    // 1. addr row inverse norms
    inv_norm_kernel<<<Nn_ / 8, 256>>>(addr);
    // 2. q_proj = query @ W^T + b
    gemm_nt<Aa, Aa, false, true><<<dim3(Aa / 128, Bq / 128), 256>>>(query, W, qptr, bias);
    // 3. row-normalize q
    qnorm_kernel<<<Bq, 128>>>();
    // 4. sim = q @ addr^T, column-scaled by inv_norm
    gemm_nt<Nn_, Aa, true, false><<<dim3(Nn_ / 128, Bq / 128), 256>>>(qptr, addr, simptr, nullptr);
    // 5. per-row top-8
    topk_kernel<<<Bq, 256>>>();
    // 6. softmax-weighted gather
    gather_kernel<<<Bq, 128>>>(data, out);
}

// round 9
// speedup vs baseline: 3.2559x; 3.2559x over previous
#include <cuda_runtime.h>
#include <cuda_bf16.h>
#include <cuda_fp16.h>
#include <math.h>
#include <stdint.h>

#define Bq   2048
#define Nn_  65536
#define Aa   512
#define Dd   512
#define TOPK 8
#define TOPC 16

// ---------------- device scratch ----------------
__device__ __half        g_simh[(size_t)Bq * Nn_];   // 256 MB sim (fp16)
__device__ float         g_q[Bq * Aa];               // normalized query fp32
__device__ __nv_bfloat16 g_qb[Bq * Aa];              // normalized query bf16
__device__ __nv_bfloat16 g_ab[(size_t)Nn_ * Aa];     // normalized addr bf16
__device__ float         g_invn[Nn_];
__device__ int           g_ci[Bq * TOPC];
__device__ float         g_tv[Bq * TOPK];
__device__ int           g_ti[Bq * TOPK];

// ---------------- helpers ----------------
__device__ __forceinline__ uint32_t smem_u32(const void* p) {
    uint32_t a;
    asm("{.reg .u64 t; cvta.to.shared.u64 t, %1; cvt.u32.u64 %0, t;}" : "=r"(a) : "l"(p));
    return a;
}
__device__ __forceinline__ void cp16(uint32_t d, const void* g) {
    asm volatile("cp.async.cg.shared.global [%0], [%1], 16;" :: "r"(d), "l"(g));
}
__device__ __forceinline__ void ldsm_x4(uint32_t* r, uint32_t addr) {
    asm volatile("ldmatrix.sync.aligned.m8n8.x4.shared.b16 {%0,%1,%2,%3}, [%4];"
                 : "=r"(r[0]), "=r"(r[1]), "=r"(r[2]), "=r"(r[3]) : "r"(addr));
}
__device__ __forceinline__ void mma_bf16(float* c, const uint32_t* a, uint32_t b0, uint32_t b1) {
    asm volatile(
        "mma.sync.aligned.m16n8k16.row.col.f32.bf16.bf16.f32 "
        "{%0,%1,%2,%3}, {%4,%5,%6,%7}, {%8,%9}, {%0,%1,%2,%3};"
        : "+f"(c[0]), "+f"(c[1]), "+f"(c[2]), "+f"(c[3])
        : "r"(a[0]), "r"(a[1]), "r"(a[2]), "r"(a[3]), "r"(b0), "r"(b1));
}
#define SW128(o) ((o) ^ (((o) >> 3) & 0x70))

// ---------------- 1. addr inverse-norm + bf16 convert (fused) ----------------
__global__ void norm_convert_kernel(const float* __restrict__ addr) {
    int warp = threadIdx.x >> 5, lane = threadIdx.x & 31;
    int row = blockIdx.x * 8 + warp;
    const float4* p = (const float4*)(addr + (size_t)row * Aa);
    float4 v[4]; float s = 0.f;
#pragma unroll
    for (int i = 0; i < 4; i++) {
        v[i] = p[lane + 32 * i];
        s += v[i].x * v[i].x + v[i].y * v[i].y + v[i].z * v[i].z + v[i].w * v[i].w;
    }
#pragma unroll
    for (int o = 16; o > 0; o >>= 1) s += __shfl_xor_sync(0xffffffffu, s, o);
    float inv = 1.f / fmaxf(sqrtf(s), 1e-12f);
    if (lane == 0) g_invn[row] = inv;
    __nv_bfloat162* ob = (__nv_bfloat162*)(g_ab + (size_t)row * Aa);
#pragma unroll
    for (int i = 0; i < 4; i++) {
        ob[(lane + 32 * i) * 2 + 0] = __floats2bfloat162_rn(v[i].x * inv, v[i].y * inv);
        ob[(lane + 32 * i) * 2 + 1] = __floats2bfloat162_rn(v[i].z * inv, v[i].w * inv);
    }
}

// ---------------- 2. projection GEMM (fp32): q = query @ W^T + b ----------------
__global__ void __launch_bounds__(256, 2)
proj_gemm(const float* __restrict__ A, const float* __restrict__ Bm,
          float* __restrict__ C, const float* __restrict__ bias)
{
    constexpr int BK = 16, K = Aa;
    __shared__ float sA[BK][128];
    __shared__ float sB[BK][128];
    const int tid = threadIdx.x;
    const int tx = tid & 15, ty = tid >> 4;
    const int m0 = blockIdx.y * 128, n0 = blockIdx.x * 128;

    float acc[8][8];
#pragma unroll
    for (int i = 0; i < 8; i++)
#pragma unroll
        for (int j = 0; j < 8; j++) acc[i][j] = 0.f;

    for (int k0 = 0; k0 < K; k0 += BK) {
#pragma unroll
        for (int i = 0; i < 2; i++) {
            int idx = tid + i * 256;
            int r = idx >> 2, c = (idx & 3) * 4;
            float4 va = *(const float4*)(A + (size_t)(m0 + r) * K + k0 + c);
            sA[c + 0][r] = va.x; sA[c + 1][r] = va.y;
            sA[c + 2][r] = va.z; sA[c + 3][r] = va.w;
            float4 vb = *(const float4*)(Bm + (size_t)(n0 + r) * K + k0 + c);
            sB[c + 0][r] = vb.x; sB[c + 1][r] = vb.y;
            sB[c + 2][r] = vb.z; sB[c + 3][r] = vb.w;
        }
        __syncthreads();
#pragma unroll
        for (int kk = 0; kk < BK; kk++) {
            float ra[8], rb[8];
            *(float4*)&ra[0] = *(const float4*)&sA[kk][ty * 8];
            *(float4*)&ra[4] = *(const float4*)&sA[kk][ty * 8 + 4];
            *(float4*)&rb[0] = *(const float4*)&sB[kk][tx * 8];
            *(float4*)&rb[4] = *(const float4*)&sB[kk][tx * 8 + 4];
#pragma unroll
            for (int i = 0; i < 8; i++)
#pragma unroll
                for (int j = 0; j < 8; j++)
                    acc[i][j] = fmaf(ra[i], rb[j], acc[i][j]);
        }
        __syncthreads();
    }
#pragma unroll
    for (int i = 0; i < 8; i++) {
        int m = m0 + ty * 8 + i;
        float* crow = C + (size_t)m * Aa + n0 + tx * 8;
        float o[8];
#pragma unroll
        for (int j = 0; j < 8; j++) o[j] = acc[i][j] + bias[n0 + tx * 8 + j];
        *(float4*)&crow[0] = *(float4*)&o[0];
        *(float4*)&crow[4] = *(float4*)&o[4];
    }
}

// ---------------- 3. q L2-normalize + bf16 convert ----------------
__global__ void qnorm_kernel() {
    int row = blockIdx.x;
    float4* p = (float4*)(g_q + (size_t)row * Aa);
    int tid = threadIdx.x;  // 128 threads
    float4 v = p[tid];
    float s = v.x * v.x + v.y * v.y + v.z * v.z + v.w * v.w;
#pragma unroll
    for (int o = 16; o > 0; o >>= 1) s += __shfl_xor_sync(0xffffffffu, s, o);
    __shared__ float ws[4];
    if ((tid & 31) == 0) ws[tid >> 5] = s;
    __syncthreads();
    float tot = ws[0] + ws[1] + ws[2] + ws[3];
    float inv = 1.f / fmaxf(sqrtf(tot), 1e-12f);
    v.x *= inv; v.y *= inv; v.z *= inv; v.w *= inv;
    p[tid] = v;
    __nv_bfloat162* qb = (__nv_bfloat162*)(g_qb + (size_t)row * Aa);
    qb[tid * 2 + 0] = __floats2bfloat162_rn(v.x, v.y);
    qb[tid * 2 + 1] = __floats2bfloat162_rn(v.z, v.w);
}

// ---------------- 4. sim GEMM: mma.sync bf16, BM=128 BN=128 BK=64, 2-stage ----------------
// dyn smem: stage s: A at s*32768, B at s*32768+16384. Total 65536 bytes.
#define SIMG_SMEM 65536

__global__ void __launch_bounds__(256, 2)
simgemm_kernel()
{
    extern __shared__ char smem[];
    uint32_t sb = smem_u32(smem);
    const int tid = threadIdx.x, lane = tid & 31, wid = tid >> 5;
    const int wm = wid & 3, wn = wid >> 2;       // 4 m-warps x 2 n-warps
    const int m0 = blockIdx.x * 128;             // 16 m tiles (fast -> addr reuse)
    const int n0 = blockIdx.y * 128;             // 512 n tiles

    float acc[2][8][4];
#pragma unroll
    for (int mi = 0; mi < 2; mi++)
#pragma unroll
        for (int ni = 0; ni < 8; ni++)
#pragma unroll
            for (int j = 0; j < 4; j++) acc[mi][ni][j] = 0.f;

    // per-stage tile loader: 128 rows x 128 B each for Q and A
    auto load_stage = [&](int s, int kt) {
        uint32_t qbase = sb + s * 32768;
        uint32_t abase = qbase + 16384;
        const char* Qg = (const char*)(g_qb) + ((size_t)m0 * Aa + kt * 64) * 2;
        const char* Ag = (const char*)(g_ab) + ((size_t)n0 * Aa + kt * 64) * 2;
#pragma unroll
        for (int u = 0; u < 4; u++) {
            int i = tid + u * 256;               // 0..1023
            int r = i >> 3, col = (i & 7) * 16;  // row, byte col
            cp16(qbase + SW128(r * 128 + col), Qg + (size_t)r * Aa * 2 + col);
            cp16(abase + SW128(r * 128 + col), Ag + (size_t)r * Aa * 2 + col);
        }
        asm volatile("cp.async.commit_group;" ::: "memory");
    };

    load_stage(0, 0);

    for (int kt = 0; kt < 8; kt++) {
        asm volatile("cp.async.wait_group 0;" ::: "memory");
        __syncthreads();
        if (kt < 7) load_stage((kt + 1) & 1, kt + 1);

        uint32_t sA = sb + (kt & 1) * 32768;
        uint32_t sB = sA + 16384;
#pragma unroll
        for (int ks = 0; ks < 4; ks++) {
            int kb = ks * 32;   // byte offset of k16 step in 128B row
            uint32_t a[2][4];
#pragma unroll
            for (int mi = 0; mi < 2; mi++) {
                int row = wm * 32 + mi * 16 + (lane & 15);
                ldsm_x4(a[mi], sA + SW128(row * 128 + kb + (lane >> 4) * 16));
            }
            uint32_t b[4][4];
#pragma unroll
            for (int nj = 0; nj < 4; nj++) {
                int nrow = wn * 64 + nj * 16 + ((lane >> 4) << 3) + (lane & 7);
                ldsm_x4(b[nj], sB + SW128(nrow * 128 + kb + ((lane >> 3) & 1) * 16));
            }
#pragma unroll
            for (int mi = 0; mi < 2; mi++)
#pragma unroll
                for (int ni = 0; ni < 8; ni++) {
                    const uint32_t* bp = &b[ni >> 1][(ni & 1) * 2];
                    mma_bf16(acc[mi][ni], a[mi], bp[0], bp[1]);
                }
        }
        __syncthreads();
    }

    // epilogue: fp32 frags -> fp16 gmem
    int rbase = m0 + wm * 32 + (lane >> 2);
    int cbase = n0 + wn * 64 + (lane & 3) * 2;
#pragma unroll
    for (int mi = 0; mi < 2; mi++) {
        int r0 = rbase + mi * 16;
#pragma unroll
        for (int ni = 0; ni < 8; ni++) {
            int col = cbase + ni * 8;
            __half2 h0 = __floats2half2_rn(acc[mi][ni][0], acc[mi][ni][1]);
            __half2 h1 = __floats2half2_rn(acc[mi][ni][2], acc[mi][ni][3]);
            *(__half2*)(g_simh + (size_t)r0 * Nn_ + col) = h0;
            *(__half2*)(g_simh + (size_t)(r0 + 8) * Nn_ + col) = h1;
        }
    }
}

// ---------------- 5. top-16 candidates per row (fp16 sims) ----------------
__global__ void __launch_bounds__(256) topk_kernel() {
    int row = blockIdx.x, tid = threadIdx.x;
    const uint4* s = (const uint4*)(g_simh + (size_t)row * Nn_);

    float lv[TOPC]; int li[TOPC];
#pragma unroll
    for (int k = 0; k < TOPC; k++) { lv[k] = -INFINITY; li[k] = 0; }

    for (int it = 0; it < Nn_ / (256 * 8); it++) {
        int vec = it * 256 + tid;
        uint4 v = s[vec];
        int base = vec * 8;
        const uint32_t* w = &v.x;
#pragma unroll
        for (int h = 0; h < 4; h++) {
            __half2 hh = *(__half2*)&w[h];
            float2 f = __half22float2(hh);
#pragma unroll
            for (int e = 0; e < 2; e++) {
                float val = e ? f.y : f.x;
                int idx = base + 2 * h + e;
                if (val > lv[TOPC - 1]) {
                    lv[TOPC - 1] = val; li[TOPC - 1] = idx;
#pragma unroll
                    for (int q = TOPC - 1; q > 0; q--) {
                        if (lv[q] > lv[q - 1]) {
                            float tv = lv[q]; lv[q] = lv[q - 1]; lv[q - 1] = tv;
                            int   ti = li[q]; li[q] = li[q - 1]; li[q - 1] = ti;
                        }
                    }
                }
            }
        }
    }

    __shared__ float sv[256 * TOPC];
    __shared__ int   si[256 * TOPC];
    __shared__ float rv[256];
    __shared__ int   rp[256];
#pragma unroll
    for (int k = 0; k < TOPC; k++) { sv[tid * TOPC + k] = lv[k]; si[tid * TOPC + k] = li[k]; }
    __syncthreads();

    for (int k = 0; k < TOPC; k++) {
        float best = -INFINITY; int bp = 0;
        for (int j = tid; j < 256 * TOPC; j += 256)
            if (sv[j] > best) { best = sv[j]; bp = j; }
        rv[tid] = best; rp[tid] = bp;
        __syncthreads();
        for (int off = 128; off > 0; off >>= 1) {
            if (tid < off && rv[tid + off] > rv[tid]) { rv[tid] = rv[tid + off]; rp[tid] = rp[tid + off]; }
            __syncthreads();
        }
        if (tid == 0) {
            g_ci[row * TOPC + k] = si[rp[0]];
            sv[rp[0]] = -INFINITY;
        }
        __syncthreads();
    }
}

// ---------------- 6. fp32 rescore of 16 candidates -> exact top-8 ----------------
__global__ void __launch_bounds__(512) rescore_kernel(const float* __restrict__ addr) {
    int row = blockIdx.x;
    int wid = threadIdx.x >> 5, lane = threadIdx.x & 31;
    __shared__ float cval[TOPC];
    __shared__ int   cidx[TOPC];
    if (threadIdx.x < TOPC) cidx[threadIdx.x] = g_ci[row * TOPC + threadIdx.x];
    __syncthreads();
    int idx = cidx[wid];
    const float4* a = (const float4*)(addr + (size_t)idx * Aa);
    const float4* q = (const float4*)(g_q + (size_t)row * Aa);
    float sum = 0.f;
#pragma unroll
    for (int i = 0; i < 4; i++) {
        float4 av = a[lane + 32 * i], qv = q[lane + 32 * i];
        sum += av.x * qv.x + av.y * qv.y + av.z * qv.z + av.w * qv.w;
    }
#pragma unroll
    for (int o = 16; o > 0; o >>= 1) sum += __shfl_xor_sync(0xffffffffu, sum, o);
    if (lane == 0) cval[wid] = sum * g_invn[idx];
    __syncthreads();
    if (threadIdx.x == 0) {
        float bv[TOPK]; int bi[TOPK];
#pragma unroll
        for (int k = 0; k < TOPK; k++) { bv[k] = -INFINITY; bi[k] = 0; }
        for (int j = 0; j < TOPC; j++) {
            float v = cval[j]; int ix = cidx[j];
            if (v > bv[TOPK - 1]) {
                bv[TOPK - 1] = v; bi[TOPK - 1] = ix;
                for (int q2 = TOPK - 1; q2 > 0; q2--) {
                    if (bv[q2] > bv[q2 - 1]) {
                        float tv = bv[q2]; bv[q2] = bv[q2 - 1]; bv[q2 - 1] = tv;
                        int   ti = bi[q2]; bi[q2] = bi[q2 - 1]; bi[q2 - 1] = ti;
                    }
                }
            }
        }
#pragma unroll
        for (int k = 0; k < TOPK; k++) { g_tv[row * TOPK + k] = bv[k]; g_ti[row * TOPK + k] = bi[k]; }
    }
}

// ---------------- 7. softmax-weighted gather ----------------
__global__ void gather_kernel(const float* __restrict__ data, float* __restrict__ out) {
    int row = blockIdx.x;
    int tid = threadIdx.x;  // 128 threads
    float w[TOPK]; int ix[TOPK];
    float m = -INFINITY;
#pragma unroll
    for (int k = 0; k < TOPK; k++) {
        w[k] = g_tv[row * TOPK + k];
        ix[k] = g_ti[row * TOPK + k];
        m = fmaxf(m, w[k]);
    }
    float sum = 0.f;
#pragma unroll
    for (int k = 0; k < TOPK; k++) { w[k] = expf((w[k] - m) * 10.f); sum += w[k]; }
    float inv = 1.f / sum;

    float4 accv = make_float4(0.f, 0.f, 0.f, 0.f);
#pragma unroll
    for (int k = 0; k < TOPK; k++) {
        float4 v = *(const float4*)(data + (size_t)ix[k] * Dd + tid * 4);
        float wk = w[k] * inv;
        accv.x += wk * v.x; accv.y += wk * v.y;
        accv.z += wk * v.z; accv.w += wk * v.w;
    }
    *(float4*)(out + (size_t)row * Dd + tid * 4) = accv;
}

// ---------------- launch ----------------
extern "C" void kernel_launch(void* const* d_in, const int* in_sizes, int n_in,
                              void* d_out, int out_size) {
    const float* query = (const float*)d_in[0];
    const float* addr  = (const float*)d_in[1];
    const float* data  = (const float*)d_in[2];
    const float* W     = (const float*)d_in[3];
    const float* bias  = (const float*)d_in[4];
    float* out = (float*)d_out;

    void* qp = nullptr;
    cudaGetSymbolAddress(&qp, g_q);
    float* qptr = (float*)qp;

    cudaFuncSetAttribute(simgemm_kernel, cudaFuncAttributeMaxDynamicSharedMemorySize, SIMG_SMEM);

    norm_convert_kernel<<<Nn_ / 8, 256>>>(addr);
    proj_gemm<<<dim3(Aa / 128, Bq / 128), 256>>>(query, W, qptr, bias);
    qnorm_kernel<<<Bq, 128>>>();
    simgemm_kernel<<<dim3(Bq / 128, Nn_ / 128), 256, SIMG_SMEM>>>();
    topk_kernel<<<Bq, 256>>>();
    rescore_kernel<<<Bq, 512>>>(addr);
    gather_kernel<<<Bq, 128>>>(data, out);
}

// round 14
// speedup vs baseline: 4.0398x; 1.2408x over previous
#include <cuda_runtime.h>
#include <cuda_bf16.h>
#include <cuda_fp16.h>
#include <math.h>
#include <stdint.h>

#define Bq   2048
#define Nn_  65536
#define Aa   512
#define Dd   512
#define TOPK 8
#define TOPC 16
#define NTILES (Nn_ / 128)      // 512
#define CPT 8                   // candidates per (row, tile)

// ---------------- device scratch ----------------
__device__ float         g_q[Bq * Aa];               // normalized query fp32
__device__ __nv_bfloat16 g_qb[Bq * Aa];              // normalized query bf16
__device__ __nv_bfloat16 g_ab[(size_t)Nn_ * Aa];     // normalized addr bf16
__device__ float         g_invn[Nn_];
__device__ float         g_cvf[(size_t)Bq * NTILES * CPT];  // 33.5 MB candidate vals
__device__ int           g_cix[(size_t)Bq * NTILES * CPT];  // 33.5 MB candidate idx
__device__ int           g_ci[Bq * TOPC];
__device__ float         g_tv[Bq * TOPK];
__device__ int           g_ti[Bq * TOPK];

// ---------------- helpers ----------------
__device__ __forceinline__ uint32_t smem_u32(const void* p) {
    uint32_t a;
    asm("{.reg .u64 t; cvta.to.shared.u64 t, %1; cvt.u32.u64 %0, t;}" : "=r"(a) : "l"(p));
    return a;
}
__device__ __forceinline__ void cp16(uint32_t d, const void* g) {
    asm volatile("cp.async.cg.shared.global [%0], [%1], 16;" :: "r"(d), "l"(g));
}
__device__ __forceinline__ void ldsm_x4(uint32_t* r, uint32_t addr) {
    asm volatile("ldmatrix.sync.aligned.m8n8.x4.shared.b16 {%0,%1,%2,%3}, [%4];"
                 : "=r"(r[0]), "=r"(r[1]), "=r"(r[2]), "=r"(r[3]) : "r"(addr));
}
__device__ __forceinline__ void mma_bf16(float* c, const uint32_t* a, uint32_t b0, uint32_t b1) {
    asm volatile(
        "mma.sync.aligned.m16n8k16.row.col.f32.bf16.bf16.f32 "
        "{%0,%1,%2,%3}, {%4,%5,%6,%7}, {%8,%9}, {%0,%1,%2,%3};"
        : "+f"(c[0]), "+f"(c[1]), "+f"(c[2]), "+f"(c[3])
        : "r"(a[0]), "r"(a[1]), "r"(a[2]), "r"(a[3]), "r"(b0), "r"(b1));
}
#define SW128(o) ((o) ^ (((o) >> 3) & 0x70))

// ---------------- 1. addr inverse-norm + bf16 convert (fused) ----------------
__global__ void norm_convert_kernel(const float* __restrict__ addr) {
    int warp = threadIdx.x >> 5, lane = threadIdx.x & 31;
    int row = blockIdx.x * 8 + warp;
    const float4* p = (const float4*)(addr + (size_t)row * Aa);
    float4 v[4]; float s = 0.f;
#pragma unroll
    for (int i = 0; i < 4; i++) {
        v[i] = p[lane + 32 * i];
        s += v[i].x * v[i].x + v[i].y * v[i].y + v[i].z * v[i].z + v[i].w * v[i].w;
    }
#pragma unroll
    for (int o = 16; o > 0; o >>= 1) s += __shfl_xor_sync(0xffffffffu, s, o);
    float inv = 1.f / fmaxf(sqrtf(s), 1e-12f);
    if (lane == 0) g_invn[row] = inv;
    __nv_bfloat162* ob = (__nv_bfloat162*)(g_ab + (size_t)row * Aa);
#pragma unroll
    for (int i = 0; i < 4; i++) {
        ob[(lane + 32 * i) * 2 + 0] = __floats2bfloat162_rn(v[i].x * inv, v[i].y * inv);
        ob[(lane + 32 * i) * 2 + 1] = __floats2bfloat162_rn(v[i].z * inv, v[i].w * inv);
    }
}

// ---------------- 2. projection GEMM (fp32): q = query @ W^T + b ----------------
__global__ void __launch_bounds__(256, 2)
proj_gemm(const float* __restrict__ A, const float* __restrict__ Bm,
          float* __restrict__ C, const float* __restrict__ bias)
{
    constexpr int BK = 16, K = Aa;
    __shared__ float sA[BK][128];
    __shared__ float sB[BK][128];
    const int tid = threadIdx.x;
    const int tx = tid & 15, ty = tid >> 4;
    const int m0 = blockIdx.y * 128, n0 = blockIdx.x * 128;

    float acc[8][8];
#pragma unroll
    for (int i = 0; i < 8; i++)
#pragma unroll
        for (int j = 0; j < 8; j++) acc[i][j] = 0.f;

    for (int k0 = 0; k0 < K; k0 += BK) {
#pragma unroll
        for (int i = 0; i < 2; i++) {
            int idx = tid + i * 256;
            int r = idx >> 2, c = (idx & 3) * 4;
            float4 va = *(const float4*)(A + (size_t)(m0 + r) * K + k0 + c);
            sA[c + 0][r] = va.x; sA[c + 1][r] = va.y;
            sA[c + 2][r] = va.z; sA[c + 3][r] = va.w;
            float4 vb = *(const float4*)(Bm + (size_t)(n0 + r) * K + k0 + c);
            sB[c + 0][r] = vb.x; sB[c + 1][r] = vb.y;
            sB[c + 2][r] = vb.z; sB[c + 3][r] = vb.w;
        }
        __syncthreads();
#pragma unroll
        for (int kk = 0; kk < BK; kk++) {
            float ra[8], rb[8];
            *(float4*)&ra[0] = *(const float4*)&sA[kk][ty * 8];
            *(float4*)&ra[4] = *(const float4*)&sA[kk][ty * 8 + 4];
            *(float4*)&rb[0] = *(const float4*)&sB[kk][tx * 8];
            *(float4*)&rb[4] = *(const float4*)&sB[kk][tx * 8 + 4];
#pragma unroll
            for (int i = 0; i < 8; i++)
#pragma unroll
                for (int j = 0; j < 8; j++)
                    acc[i][j] = fmaf(ra[i], rb[j], acc[i][j]);
        }
        __syncthreads();
    }
#pragma unroll
    for (int i = 0; i < 8; i++) {
        int m = m0 + ty * 8 + i;
        float* crow = C + (size_t)m * Aa + n0 + tx * 8;
        float o[8];
#pragma unroll
        for (int j = 0; j < 8; j++) o[j] = acc[i][j] + bias[n0 + tx * 8 + j];
        *(float4*)&crow[0] = *(float4*)&o[0];
        *(float4*)&crow[4] = *(float4*)&o[4];
    }
}

// ---------------- 3. q L2-normalize + bf16 convert ----------------
__global__ void qnorm_kernel() {
    int row = blockIdx.x;
    float4* p = (float4*)(g_q + (size_t)row * Aa);
    int tid = threadIdx.x;  // 128 threads
    float4 v = p[tid];
    float s = v.x * v.x + v.y * v.y + v.z * v.z + v.w * v.w;
#pragma unroll
    for (int o = 16; o > 0; o >>= 1) s += __shfl_xor_sync(0xffffffffu, s, o);
    __shared__ float ws[4];
    if ((tid & 31) == 0) ws[tid >> 5] = s;
    __syncthreads();
    float tot = ws[0] + ws[1] + ws[2] + ws[3];
    float inv = 1.f / fmaxf(sqrtf(tot), 1e-12f);
    v.x *= inv; v.y *= inv; v.z *= inv; v.w *= inv;
    p[tid] = v;
    __nv_bfloat162* qb = (__nv_bfloat162*)(g_qb + (size_t)row * Aa);
    qb[tid * 2 + 0] = __floats2bfloat162_rn(v.x, v.y);
    qb[tid * 2 + 1] = __floats2bfloat162_rn(v.z, v.w);
}

// ---------------- 4. sim GEMM + fused per-slice top-8 candidates ----------------
// dyn smem: stage s: Q at s*32768, A at s*32768+16384. Total 65536 bytes.
// Epilogue reuses smem as a 128 x 132-half staging tile (33792 B).
#define SIMG_SMEM 65536
#define SPITCH 132

__global__ void __launch_bounds__(256, 2)
simgemm_kernel()
{
    extern __shared__ char smem[];
    uint32_t sb = smem_u32(smem);
    const int tid = threadIdx.x, lane = tid & 31, wid = tid >> 5;
    const int wm = wid & 3, wn = wid >> 2;       // 4 m-warps x 2 n-warps
    const int m0 = blockIdx.x * 128;             // 16 m tiles (fast -> addr reuse)
    const int n0 = blockIdx.y * 128;             // 512 n tiles

    float acc[2][8][4];
#pragma unroll
    for (int mi = 0; mi < 2; mi++)
#pragma unroll
        for (int ni = 0; ni < 8; ni++)
#pragma unroll
            for (int j = 0; j < 4; j++) acc[mi][ni][j] = 0.f;

    auto load_stage = [&](int s, int kt) {
        uint32_t qbase = sb + s * 32768;
        uint32_t abase = qbase + 16384;
        const char* Qg = (const char*)(g_qb) + ((size_t)m0 * Aa + kt * 64) * 2;
        const char* Ag = (const char*)(g_ab) + ((size_t)n0 * Aa + kt * 64) * 2;
#pragma unroll
        for (int u = 0; u < 4; u++) {
            int i = tid + u * 256;
            int r = i >> 3, col = (i & 7) * 16;
            cp16(qbase + SW128(r * 128 + col), Qg + (size_t)r * Aa * 2 + col);
            cp16(abase + SW128(r * 128 + col), Ag + (size_t)r * Aa * 2 + col);
        }
        asm volatile("cp.async.commit_group;" ::: "memory");
    };

    load_stage(0, 0);

    for (int kt = 0; kt < 8; kt++) {
        asm volatile("cp.async.wait_group 0;" ::: "memory");
        __syncthreads();
        if (kt < 7) load_stage((kt + 1) & 1, kt + 1);

        uint32_t sA = sb + (kt & 1) * 32768;
        uint32_t sB = sA + 16384;
#pragma unroll
        for (int ks = 0; ks < 4; ks++) {
            int kb = ks * 32;
            uint32_t a[2][4];
#pragma unroll
            for (int mi = 0; mi < 2; mi++) {
                int row = wm * 32 + mi * 16 + (lane & 15);
                ldsm_x4(a[mi], sA + SW128(row * 128 + kb + (lane >> 4) * 16));
            }
            uint32_t b[4][4];
#pragma unroll
            for (int nj = 0; nj < 4; nj++) {
                int nrow = wn * 64 + nj * 16 + ((lane >> 4) << 3) + (lane & 7);
                ldsm_x4(b[nj], sB + SW128(nrow * 128 + kb + ((lane >> 3) & 1) * 16));
            }
#pragma unroll
            for (int mi = 0; mi < 2; mi++)
#pragma unroll
                for (int ni = 0; ni < 8; ni++) {
                    const uint32_t* bp = &b[ni >> 1][(ni & 1) * 2];
                    mma_bf16(acc[mi][ni], a[mi], bp[0], bp[1]);
                }
        }
        __syncthreads();
    }

    // ---- epilogue: stage fp16 tile to smem ----
    __half* st = (__half*)smem;
    {
        int r0 = wm * 32 + (lane >> 2);
        int c0 = wn * 64 + (lane & 3) * 2;
#pragma unroll
        for (int mi = 0; mi < 2; mi++) {
            int r = r0 + mi * 16;
#pragma unroll
            for (int ni = 0; ni < 8; ni++) {
                int col = c0 + ni * 8;
                *(__half2*)(st + r * SPITCH + col) =
                    __floats2half2_rn(acc[mi][ni][0], acc[mi][ni][1]);
                *(__half2*)(st + (r + 8) * SPITCH + col) =
                    __floats2half2_rn(acc[mi][ni][2], acc[mi][ni][3]);
            }
        }
    }
    __syncthreads();

    // ---- per-row top-8 of this 128-col slice (2 threads per row) ----
    {
        int rl = tid >> 1, h = tid & 1;
        const __half* rowp = st + rl * SPITCH + h * 64;
        float lv[CPT]; int li[CPT];
#pragma unroll
        for (int k = 0; k < CPT; k++) { lv[k] = -INFINITY; li[k] = 0; }
        for (int c = 0; c < 64; c++) {
            float v = __half2float(rowp[c]);
            if (v > lv[CPT - 1]) {
                lv[CPT - 1] = v; li[CPT - 1] = n0 + h * 64 + c;
#pragma unroll
                for (int q = CPT - 1; q > 0; q--) {
                    if (lv[q] > lv[q - 1]) {
                        float tv = lv[q]; lv[q] = lv[q - 1]; lv[q - 1] = tv;
                        int   ti = li[q]; li[q] = li[q - 1]; li[q - 1] = ti;
                    }
                }
            }
        }
        // merge partner's 8 (lane^1 is the other half of the same row)
        float ov[CPT]; int oi[CPT];
#pragma unroll
        for (int k = 0; k < CPT; k++) {
            ov[k] = __shfl_xor_sync(0xffffffffu, lv[k], 1);
            oi[k] = __shfl_xor_sync(0xffffffffu, li[k], 1);
        }
        if (h == 0) {
#pragma unroll
            for (int k = 0; k < CPT; k++) {
                float v = ov[k];
                if (v > lv[CPT - 1]) {
                    lv[CPT - 1] = v; li[CPT - 1] = oi[k];
#pragma unroll
                    for (int q = CPT - 1; q > 0; q--) {
                        if (lv[q] > lv[q - 1]) {
                            float tv = lv[q]; lv[q] = lv[q - 1]; lv[q - 1] = tv;
                            int   ti = li[q]; li[q] = li[q - 1]; li[q - 1] = ti;
                        }
                    }
                }
            }
            size_t base = ((size_t)(m0 + rl) * NTILES + blockIdx.y) * CPT;
#pragma unroll
            for (int k = 0; k < CPT; k++) {
                g_cvf[base + k] = lv[k];
                g_cix[base + k] = li[k];
            }
        }
    }
}

// ---------------- 5. reduce 4096 candidates/row -> top-16 ----------------
__global__ void __launch_bounds__(256) cand_reduce_kernel() {
    int row = blockIdx.x, tid = threadIdx.x;
    const float* cv = g_cvf + (size_t)row * NTILES * CPT;
    const int*   cx = g_cix + (size_t)row * NTILES * CPT;

    float lv[TOPC]; int li[TOPC];
#pragma unroll
    for (int k = 0; k < TOPC; k++) { lv[k] = -INFINITY; li[k] = 0; }

#pragma unroll
    for (int i = 0; i < NTILES * CPT / 256; i++) {   // 16 entries per thread
        int j = tid + i * 256;
        float v = cv[j]; int ix = cx[j];
        if (v > lv[TOPC - 1]) {
            lv[TOPC - 1] = v; li[TOPC - 1] = ix;
#pragma unroll
            for (int q = TOPC - 1; q > 0; q--) {
                if (lv[q] > lv[q - 1]) {
                    float tv = lv[q]; lv[q] = lv[q - 1]; lv[q - 1] = tv;
                    int   ti = li[q]; li[q] = li[q - 1]; li[q - 1] = ti;
                }
            }
        }
    }

    __shared__ float sv[256 * TOPC];
    __shared__ int   si[256 * TOPC];
    __shared__ float rv[256];
    __shared__ int   rp[256];
#pragma unroll
    for (int k = 0; k < TOPC; k++) { sv[tid * TOPC + k] = lv[k]; si[tid * TOPC + k] = li[k]; }
    __syncthreads();

    for (int k = 0; k < TOPC; k++) {
        float best = -INFINITY; int bp = 0;
        for (int j = tid; j < 256 * TOPC; j += 256)
            if (sv[j] > best) { best = sv[j]; bp = j; }
        rv[tid] = best; rp[tid] = bp;
        __syncthreads();
        for (int off = 128; off > 0; off >>= 1) {
            if (tid < off && rv[tid + off] > rv[tid]) { rv[tid] = rv[tid + off]; rp[tid] = rp[tid + off]; }
            __syncthreads();
        }
        if (tid == 0) {
            g_ci[row * TOPC + k] = si[rp[0]];
            sv[rp[0]] = -INFINITY;
        }
        __syncthreads();
    }
}

// ---------------- 6. fp32 rescore of 16 candidates -> exact top-8 ----------------
__global__ void __launch_bounds__(512) rescore_kernel(const float* __restrict__ addr) {
    int row = blockIdx.x;
    int wid = threadIdx.x >> 5, lane = threadIdx.x & 31;
    __shared__ float cval[TOPC];
    __shared__ int   cidx[TOPC];
    if (threadIdx.x < TOPC) cidx[threadIdx.x] = g_ci[row * TOPC + threadIdx.x];
    __syncthreads();
    int idx = cidx[wid];
    const float4* a = (const float4*)(addr + (size_t)idx * Aa);
    const float4* q = (const float4*)(g_q + (size_t)row * Aa);
    float sum = 0.f;
#pragma unroll
    for (int i = 0; i < 4; i++) {
        float4 av = a[lane + 32 * i], qv = q[lane + 32 * i];
        sum += av.x * qv.x + av.y * qv.y + av.z * qv.z + av.w * qv.w;
    }
#pragma unroll
    for (int o = 16; o > 0; o >>= 1) sum += __shfl_xor_sync(0xffffffffu, sum, o);
    if (lane == 0) cval[wid] = sum * g_invn[idx];
    __syncthreads();
    if (threadIdx.x == 0) {
        float bv[TOPK]; int bi[TOPK];
#pragma unroll
        for (int k = 0; k < TOPK; k++) { bv[k] = -INFINITY; bi[k] = 0; }
        for (int j = 0; j < TOPC; j++) {
            float v = cval[j]; int ix = cidx[j];
            if (v > bv[TOPK - 1]) {
                bv[TOPK - 1] = v; bi[TOPK - 1] = ix;
                for (int q2 = TOPK - 1; q2 > 0; q2--) {
                    if (bv[q2] > bv[q2 - 1]) {
                        float tv = bv[q2]; bv[q2] = bv[q2 - 1]; bv[q2 - 1] = tv;
                        int   ti = bi[q2]; bi[q2] = bi[q2 - 1]; bi[q2 - 1] = ti;
                    }
                }
            }
        }
#pragma unroll
        for (int k = 0; k < TOPK; k++) { g_tv[row * TOPK + k] = bv[k]; g_ti[row * TOPK + k] = bi[k]; }
    }
}

// ---------------- 7. softmax-weighted gather ----------------
__global__ void gather_kernel(const float* __restrict__ data, float* __restrict__ out) {
    int row = blockIdx.x;
    int tid = threadIdx.x;  // 128 threads
    float w[TOPK]; int ix[TOPK];
    float m = -INFINITY;
#pragma unroll
    for (int k = 0; k < TOPK; k++) {
        w[k] = g_tv[row * TOPK + k];
        ix[k] = g_ti[row * TOPK + k];
        m = fmaxf(m, w[k]);
    }
    float sum = 0.f;
#pragma unroll
    for (int k = 0; k < TOPK; k++) { w[k] = expf((w[k] - m) * 10.f); sum += w[k]; }
    float inv = 1.f / sum;

    float4 accv = make_float4(0.f, 0.f, 0.f, 0.f);
#pragma unroll
    for (int k = 0; k < TOPK; k++) {
        float4 v = *(const float4*)(data + (size_t)ix[k] * Dd + tid * 4);
        float wk = w[k] * inv;
        accv.x += wk * v.x; accv.y += wk * v.y;
        accv.z += wk * v.z; accv.w += wk * v.w;
    }
    *(float4*)(out + (size_t)row * Dd + tid * 4) = accv;
}

// ---------------- launch ----------------
extern "C" void kernel_launch(void* const* d_in, const int* in_sizes, int n_in,
                              void* d_out, int out_size) {
    const float* query = (const float*)d_in[0];
    const float* addr  = (const float*)d_in[1];
    const float* data  = (const float*)d_in[2];
    const float* W     = (const float*)d_in[3];
    const float* bias  = (const float*)d_in[4];
    float* out = (float*)d_out;

    void* qp = nullptr;
    cudaGetSymbolAddress(&qp, g_q);
    float* qptr = (float*)qp;

    cudaFuncSetAttribute(simgemm_kernel, cudaFuncAttributeMaxDynamicSharedMemorySize, SIMG_SMEM);

    norm_convert_kernel<<<Nn_ / 8, 256>>>(addr);
    proj_gemm<<<dim3(Aa / 128, Bq / 128), 256>>>(query, W, qptr, bias);
    qnorm_kernel<<<Bq, 128>>>();
    simgemm_kernel<<<dim3(Bq / 128, Nn_ / 128), 256, SIMG_SMEM>>>();
    cand_reduce_kernel<<<Bq, 256>>>();
    rescore_kernel<<<Bq, 512>>>(addr);
    gather_kernel<<<Bq, 128>>>(data, out);
}